// round 2
// baseline (speedup 1.0000x reference)
#include <cuda_runtime.h>
#include <cuda_bf16.h>
#include <math.h>

// Problem constants
#define T_STEPS 100
#define BATCH   64
#define NINP    400
#define NHID    1150
#define G4      (4*NHID)       // 4600
#define NTOKEN  33278
#define MB      (T_STEPS*BATCH) // 6400 rows

// ---------------------------------------------------------------------------
// Scratch (static device allocations; allocation-free at runtime)
// ---------------------------------------------------------------------------
__device__ float g_x0 [MB * 2*NINP];      // [6400, 800]  embedded input
__device__ float g_xg [MB * G4];          // [6400, 4600] precomputed input gates (reused per layer)
__device__ float g_hs1[MB * NHID];        // [6400, 1150]
__device__ float g_hs2[MB * NHID];
__device__ float g_att[MB * NHID];
__device__ float g_h  [2 * BATCH * NHID]; // ping-pong
__device__ float g_c  [2 * BATCH * NHID];

// ---------------------------------------------------------------------------
// Embedding: x0[m, 0:400] = emb_W[input[m]], x0[m, 400:800] = emb_W[input2[m]]
// ---------------------------------------------------------------------------
__global__ void embed_kernel(const int* __restrict__ in1, const int* __restrict__ in2,
                             const float* __restrict__ embW, float* __restrict__ x0)
{
    int m = blockIdx.x;
    int i1 = in1[m];
    int i2 = in2[m];
    const float* e1 = embW + (size_t)i1 * NINP;
    const float* e2 = embW + (size_t)i2 * NINP;
    float* row = x0 + (size_t)m * (2*NINP);
    for (int k = threadIdx.x; k < NINP; k += blockDim.x) {
        row[k]        = e1[k];
        row[NINP + k] = e2[k];
    }
}

// ---------------------------------------------------------------------------
// Copy initial h/c into ping buffers
// ---------------------------------------------------------------------------
__global__ void copy2_kernel(const float* __restrict__ a, const float* __restrict__ b,
                             float* __restrict__ da, float* __restrict__ db, int n)
{
    int i = blockIdx.x * blockDim.x + threadIdx.x;
    if (i < n) { da[i] = a[i]; db[i] = b[i]; }
}

// ---------------------------------------------------------------------------
// Generic NT GEMM: C[m,n] = sum_k A[m*K+k]*B[n*K+k] (+ bias1[n] + bias2[n])
// Tile 128x64x8, thread tile 8x4, 256 threads.
// ---------------------------------------------------------------------------
__global__ __launch_bounds__(256)
void gemm_nt_kernel(const float* __restrict__ A, const float* __restrict__ B,
                    float* __restrict__ C, int M, int N, int K,
                    const float* __restrict__ bias1, const float* __restrict__ bias2)
{
    const int BM = 128, BN = 64, BK = 8, TM = 8, TN = 4;
    __shared__ float As[BK][BM + 4];
    __shared__ float Bs[BK][BN + 4];

    int m0 = blockIdx.y * BM;
    int n0 = blockIdx.x * BN;
    int tid = threadIdx.x;
    int tr = tid / 16;          // 0..15
    int tc = tid % 16;          // 0..15

    // loader mapping
    int aRow = tid / 2;         // 0..127
    int aK   = (tid % 2) * 4;   // 0 or 4
    int bRow = tid / 4;         // 0..63
    int bK   = (tid % 4) * 2;   // 0,2,4,6

    float acc[TM][TN];
    #pragma unroll
    for (int i = 0; i < TM; i++)
        #pragma unroll
        for (int j = 0; j < TN; j++) acc[i][j] = 0.f;

    const int mA = m0 + aRow;
    const int nB = n0 + bRow;

    for (int k0 = 0; k0 < K; k0 += BK) {
        #pragma unroll
        for (int i = 0; i < 4; i++) {
            int k = k0 + aK + i;
            As[aK + i][aRow] = (k < K && mA < M) ? A[(size_t)mA * K + k] : 0.f;
        }
        #pragma unroll
        for (int i = 0; i < 2; i++) {
            int k = k0 + bK + i;
            Bs[bK + i][bRow] = (k < K && nB < N) ? B[(size_t)nB * K + k] : 0.f;
        }
        __syncthreads();
        #pragma unroll
        for (int kk = 0; kk < BK; kk++) {
            float ra[TM], rb[TN];
            #pragma unroll
            for (int i = 0; i < TM; i++) ra[i] = As[kk][tr * TM + i];
            #pragma unroll
            for (int j = 0; j < TN; j++) rb[j] = Bs[kk][tc * TN + j];
            #pragma unroll
            for (int i = 0; i < TM; i++)
                #pragma unroll
                for (int j = 0; j < TN; j++)
                    acc[i][j] += ra[i] * rb[j];
        }
        __syncthreads();
    }

    #pragma unroll
    for (int i = 0; i < TM; i++) {
        int m = m0 + tr * TM + i;
        if (m >= M) continue;
        #pragma unroll
        for (int j = 0; j < TN; j++) {
            int n = n0 + tc * TN + j;
            if (n >= N) continue;
            float v = acc[i][j];
            if (bias1) v += bias1[n];
            if (bias2) v += bias2[n];
            C[(size_t)m * N + n] = v;
        }
    }
}

// ---------------------------------------------------------------------------
// Fused LSTM step: gates = Xg[t] + h_in @ Whh^T, then activations + c/h update.
// Gate columns interleaved: CTA handles 8 j's x 4 gates = 32 columns, all 64 rows.
// grid = ceil(1150/8) = 144 CTAs, 256 threads.
// Thread (trow 0..31, tcol 0..7): rows trow*2+{0,1}, one j (all 4 gates).
// ---------------------------------------------------------------------------
__global__ __launch_bounds__(256)
void lstm_step_kernel(const float* __restrict__ xg,    // [64, 4600] (biases folded in)
                      const float* __restrict__ Whh,   // [4600, 1150]
                      const float* __restrict__ h_in,  // [64, 1150]
                      const float* __restrict__ c_in,  // [64, 1150]
                      float* __restrict__ h_out,
                      float* __restrict__ c_out,
                      float* __restrict__ hs_out)      // [64, 1150] slice of hs[t]
{
    const int H = NHID;
    __shared__ float As[16][68];  // [k][b]
    __shared__ float Bs[16][36];  // [k][col], col = jl*4 + gate

    int j0   = blockIdx.x * 8;
    int tid  = threadIdx.x;
    int tcol = tid % 8;
    int trow = tid / 8;

    // loader mapping
    int aRow = tid / 4;          // 0..63
    int aK   = (tid % 4) * 4;
    int bCol = tid / 8;          // 0..31
    int bK   = (tid % 8) * 2;
    int jB   = j0 + bCol / 4;
    int gB   = bCol % 4;
    const float* wrow = (jB < H) ? (Whh + (size_t)(gB * H + jB) * H) : Whh;
    bool wvalid = (jB < H);

    float acc[2][4];
    #pragma unroll
    for (int r = 0; r < 2; r++)
        #pragma unroll
        for (int g = 0; g < 4; g++) acc[r][g] = 0.f;

    for (int k0 = 0; k0 < H; k0 += 16) {
        #pragma unroll
        for (int i = 0; i < 4; i++) {
            int k = k0 + aK + i;
            As[aK + i][aRow] = (k < H) ? h_in[aRow * H + k] : 0.f;
        }
        #pragma unroll
        for (int i = 0; i < 2; i++) {
            int k = k0 + bK + i;
            Bs[bK + i][bCol] = (wvalid && k < H) ? wrow[k] : 0.f;
        }
        __syncthreads();
        #pragma unroll
        for (int kk = 0; kk < 16; kk++) {
            float a0 = As[kk][trow * 2 + 0];
            float a1 = As[kk][trow * 2 + 1];
            float b0 = Bs[kk][tcol * 4 + 0];
            float b1 = Bs[kk][tcol * 4 + 1];
            float b2 = Bs[kk][tcol * 4 + 2];
            float b3 = Bs[kk][tcol * 4 + 3];
            acc[0][0] += a0 * b0; acc[0][1] += a0 * b1;
            acc[0][2] += a0 * b2; acc[0][3] += a0 * b3;
            acc[1][0] += a1 * b0; acc[1][1] += a1 * b1;
            acc[1][2] += a1 * b2; acc[1][3] += a1 * b3;
        }
        __syncthreads();
    }

    int j = j0 + tcol;
    if (j < H) {
        #pragma unroll
        for (int r = 0; r < 2; r++) {
            int b = trow * 2 + r;
            const float* x = xg + (size_t)b * G4;
            float vi = acc[r][0] + x[j];
            float vf = acc[r][1] + x[H + j];
            float vg = acc[r][2] + x[2 * H + j];
            float vo = acc[r][3] + x[3 * H + j];
            float ii = 1.f / (1.f + expf(-vi));
            float ff = 1.f / (1.f + expf(-vf));
            float gg = tanhf(vg);
            float oo = 1.f / (1.f + expf(-vo));
            float cn = ff * c_in[b * H + j] + ii * gg;
            float hn = oo * tanhf(cn);
            c_out[b * H + j] = cn;
            h_out[b * H + j] = hn;
            hs_out[b * H + j] = hn;
        }
    }
}

// ---------------------------------------------------------------------------
// Fused causal attention: one CTA per (b, t).
// scores[s] = <h_t, h_s> (s<=t); softmax; out[t,b,:] = sum_s attn[s] * h_s.
// ---------------------------------------------------------------------------
__global__ __launch_bounds__(128)
void attention_kernel(const float* __restrict__ hs, float* __restrict__ out)
{
    int b = blockIdx.x;
    int t = blockIdx.y;
    const int H = NHID;
    __shared__ float ht[NHID];
    __shared__ float sc[T_STEPS];
    __shared__ float red[128];
    int tid = threadIdx.x;

    const float* hsb = hs + (size_t)b * H;  // index by + s*BATCH*H

    for (int k = tid; k < H; k += 128)
        ht[k] = hsb[(size_t)t * BATCH * H + k];
    __syncthreads();

    float lmax = -1e30f;
    for (int s = tid; s <= t; s += 128) {
        const float* row = hsb + (size_t)s * BATCH * H;
        float d = 0.f;
        for (int k = 0; k < H; k++) d += ht[k] * row[k];
        sc[s] = d;
        lmax = fmaxf(lmax, d);
    }
    red[tid] = lmax;
    __syncthreads();
    #pragma unroll
    for (int off = 64; off > 0; off >>= 1) {
        if (tid < off) red[tid] = fmaxf(red[tid], red[tid + off]);
        __syncthreads();
    }
    float mx = red[0];
    __syncthreads();

    float lsum = 0.f;
    for (int s = tid; s <= t; s += 128) {
        float e = expf(sc[s] - mx);
        sc[s] = e;
        lsum += e;
    }
    red[tid] = lsum;
    __syncthreads();
    #pragma unroll
    for (int off = 64; off > 0; off >>= 1) {
        if (tid < off) red[tid] += red[tid + off];
        __syncthreads();
    }
    float inv = 1.f / red[0];
    __syncthreads();

    for (int h = tid; h < H; h += 128) {
        float a = 0.f;
        for (int s = 0; s <= t; s++)
            a += sc[s] * hsb[(size_t)s * BATCH * H + h];
        out[((size_t)t * BATCH + b) * H + h] = a * inv;
    }
}

// ---------------------------------------------------------------------------
// Launch
// ---------------------------------------------------------------------------
static float* sym_addr(const void* sym)
{
    void* p = nullptr;
    cudaGetSymbolAddress(&p, sym);
    return (float*)p;
}

extern "C" void kernel_launch(void* const* d_in, const int* in_sizes, int n_in,
                              void* d_out, int out_size)
{
    const int*   in1  = (const int*)d_in[0];
    const int*   in2  = (const int*)d_in[1];
    const float* hc0[6] = { (const float*)d_in[2], (const float*)d_in[3],
                            (const float*)d_in[4], (const float*)d_in[5],
                            (const float*)d_in[6], (const float*)d_in[7] };
    const float* embW = (const float*)d_in[8];
    const float* W_ih[3], *W_hh[3], *b_ih[3], *b_hh[3];
    for (int l = 0; l < 3; l++) {
        W_ih[l] = (const float*)d_in[9  + 4*l];
        W_hh[l] = (const float*)d_in[10 + 4*l];
        b_ih[l] = (const float*)d_in[11 + 4*l];
        b_hh[l] = (const float*)d_in[12 + 4*l];
    }
    const float* decW = (const float*)d_in[21];
    const float* decb = (const float*)d_in[22];
    float* out = (float*)d_out;

    float* x0  = sym_addr(g_x0);
    float* xg  = sym_addr(g_xg);
    float* hs1 = sym_addr(g_hs1);
    float* hs2 = sym_addr(g_hs2);
    float* att = sym_addr(g_att);
    float* hbuf = sym_addr(g_h);
    float* cbuf = sym_addr(g_c);
    const int HC = BATCH * NHID; // 73600

    // 1. Embedding
    embed_kernel<<<MB, 256>>>(in1, in2, embW, x0);

    const float* layer_in[3]  = { x0, hs1, hs2 };
    const int    layer_K[3]   = { 2*NINP, NHID, NHID };
    float*       layer_out[3] = { hs1, hs2, hs1 };

    for (int l = 0; l < 3; l++) {
        // 2. Input gates for all timesteps: Xg = X @ W_ih^T + b_ih + b_hh
        dim3 grid((G4 + 63) / 64, (MB + 127) / 128);
        gemm_nt_kernel<<<grid, 256>>>(layer_in[l], W_ih[l], xg,
                                      MB, G4, layer_K[l], b_ih[l], b_hh[l]);
        // 3. init h/c ping buffers
        copy2_kernel<<<(HC + 255) / 256, 256>>>(hc0[2*l], hc0[2*l + 1],
                                                hbuf, cbuf, HC);
        // 4. sequential recurrence
        for (int t = 0; t < T_STEPS; t++) {
            float* h_in  = hbuf + (t & 1) * HC;
            float* c_in  = cbuf + (t & 1) * HC;
            float* h_out = hbuf + ((t + 1) & 1) * HC;
            float* c_out = cbuf + ((t + 1) & 1) * HC;
            lstm_step_kernel<<<(NHID + 7) / 8, 256>>>(
                xg + (size_t)t * BATCH * G4, W_hh[l],
                h_in, c_in, h_out, c_out,
                layer_out[l] + (size_t)t * BATCH * NHID);
        }
    }

    // 5. Causal attention over last layer's hidden states (in hs1)
    attention_kernel<<<dim3(BATCH, T_STEPS), 128>>>(hs1, att);

    // 6. Decoder: out = att.reshape(6400,1150) @ dec_W^T + dec_b
    dim3 dgrid((NTOKEN + 63) / 64, (MB + 127) / 128);
    gemm_nt_kernel<<<dgrid, 256>>>(att, decW, out, MB, NTOKEN, NHID, decb, nullptr);
}

// round 5
// speedup vs baseline: 2.3417x; 2.3417x over previous
#include <cuda_runtime.h>
#include <cuda_bf16.h>
#include <cstdint>
#include <math.h>

#define T_STEPS 100
#define BATCH   64
#define NINP    400
#define NHID    1150
#define G4P     4608
#define NTOKEN  33278
#define NTOK_P  33280
#define MB      6400
#define KP      1152

// ---------------- static scratch ----------------
__device__ __align__(128) float g_x0 [MB * 2*NINP];
__device__ __align__(128) float g_xg [(size_t)MB * G4P];
__device__ __align__(128) float g_hs1[MB * NHID];
__device__ __align__(128) float g_hs2[MB * NHID];
__device__ __align__(128) float g_att[MB * NHID];
__device__ __align__(128) __nv_bfloat16 g_a_hi [MB * KP];
__device__ __align__(128) __nv_bfloat16 g_a_lo [MB * KP];
__device__ __align__(128) __nv_bfloat16 g_dec_hi[(size_t)NTOK_P * KP];
__device__ __align__(128) __nv_bfloat16 g_dec_lo[(size_t)NTOK_P * KP];
__device__ __align__(128) __nv_bfloat16 g_wih_hi[G4P * KP];
__device__ __align__(128) __nv_bfloat16 g_wih_lo[G4P * KP];
__device__ __align__(128) __nv_bfloat16 g_whh_hi[G4P * KP];
__device__ __align__(128) __nv_bfloat16 g_whh_lo[G4P * KP];
__device__ __align__(128) __nv_bfloat16 g_h_hi[2 * 64 * KP];
__device__ __align__(128) __nv_bfloat16 g_h_lo[2 * 64 * KP];
__device__ __align__(128) float g_c[2 * BATCH * NHID];
__device__ __align__(128) float g_bperm[G4P];

// ---------------- PTX helpers ----------------
__device__ __forceinline__ uint32_t smem_to_u32(const void* p) {
    uint32_t a;
    asm("{ .reg .u64 t; cvta.to.shared.u64 t, %1; cvt.u32.u64 %0, t; }" : "=r"(a) : "l"(p));
    return a;
}
__device__ __forceinline__ void cp16(uint32_t d, const void* s) {
    asm volatile("cp.async.cg.shared.global [%0], [%1], 16;" :: "r"(d), "l"(s));
}
#define CP_COMMIT() asm volatile("cp.async.commit_group;" ::: "memory")
#define CP_WAIT(n)  asm volatile("cp.async.wait_group %0;" :: "n"(n) : "memory")

__device__ __forceinline__ void ldm4(uint32_t a, uint32_t r[4]) {
    asm volatile("ldmatrix.sync.aligned.m8n8.x4.shared.b16 {%0,%1,%2,%3}, [%4];"
        : "=r"(r[0]), "=r"(r[1]), "=r"(r[2]), "=r"(r[3]) : "r"(a));
}
__device__ __forceinline__ void mma16816(float c[4], const uint32_t a[4], uint32_t b0, uint32_t b1) {
    asm volatile("mma.sync.aligned.m16n8k16.row.col.f32.bf16.bf16.f32 "
        "{%0,%1,%2,%3},{%4,%5,%6,%7},{%8,%9},{%0,%1,%2,%3};"
        : "+f"(c[0]), "+f"(c[1]), "+f"(c[2]), "+f"(c[3])
        : "r"(a[0]), "r"(a[1]), "r"(a[2]), "r"(a[3]), "r"(b0), "r"(b1));
}

// ============================================================================
// HMMA GEMM: C[M x N] = A * B^T (+bias). Tile 128x128, BK=32, 256 threads.
// A/B stored as [rows, KP] bf16 hi/lo. Smem rows padded to 40 elems (80 B).
// ============================================================================
__global__ __launch_bounds__(256, 1)
void hmma_gemm(const __nv_bfloat16* __restrict__ aHi, const __nv_bfloat16* __restrict__ aLo,
               const __nv_bfloat16* __restrict__ bHi, const __nv_bfloat16* __restrict__ bLo,
               float* __restrict__ C, const float* __restrict__ bias,
               int nk, int Nvalid, int ldc)
{
    extern __shared__ __align__(16) char smem[];
    uint32_t sb = smem_to_u32(smem);
    const int tid = threadIdx.x, lane = tid & 31, wid = tid >> 5;
    const int RB = (wid & 1) * 64, CB = (wid >> 1) * 32;
    const int m0 = blockIdx.x * 128, n0 = blockIdx.y * 128;
    const int STAGE = 40960, TILE = 10240;

    float c[4][4][4];
    #pragma unroll
    for (int i = 0; i < 4; i++)
        #pragma unroll
        for (int j = 0; j < 4; j++)
            #pragma unroll
            for (int k = 0; k < 4; k++) c[i][j][k] = 0.f;

    auto load_chunk = [&](int kc, uint32_t stg) {
        #pragma unroll
        for (int i = 0; i < 8; i++) {
            int idx = tid + i * 256;
            int tile = idx >> 9, w = idx & 511, row = w >> 2, cc = w & 3;
            const __nv_bfloat16* g = (tile == 0) ? aHi : (tile == 1) ? aLo : (tile == 2) ? bHi : bLo;
            int grow = ((tile < 2) ? m0 : n0) + row;
            cp16(stg + tile * TILE + row * 80 + cc * 16,
                 g + (size_t)grow * KP + kc * 32 + cc * 8);
        }
        CP_COMMIT();
    };

    auto compute = [&](uint32_t stg) {
        #pragma unroll
        for (int ks = 0; ks < 2; ks++) {
            int kb = ks * 16;
            uint32_t Ah[4][4], Al[4][4], Bh[2][4], Bl[2][4];
            #pragma unroll
            for (int mi = 0; mi < 4; mi++) {
                uint32_t off = (uint32_t)(RB + mi * 16 + (lane & 15)) * 80
                             + (uint32_t)(kb + ((lane >> 4) << 3)) * 2;
                ldm4(stg + off, Ah[mi]);
                ldm4(stg + TILE + off, Al[mi]);
            }
            #pragma unroll
            for (int g2 = 0; g2 < 2; g2++) {
                uint32_t nrow = CB + g2 * 16 + (lane & 7) + ((lane >> 4) & 1) * 8;
                uint32_t off = nrow * 80 + (uint32_t)(kb + ((lane >> 3) & 1) * 8) * 2;
                ldm4(stg + 2 * TILE + off, Bh[g2]);
                ldm4(stg + 3 * TILE + off, Bl[g2]);
            }
            #pragma unroll
            for (int mi = 0; mi < 4; mi++)
                #pragma unroll
                for (int ni = 0; ni < 4; ni++) {
                    int g2 = ni >> 1, hf = (ni & 1) * 2;
                    mma16816(c[mi][ni], Ah[mi], Bh[g2][hf], Bh[g2][hf + 1]);
                    mma16816(c[mi][ni], Ah[mi], Bl[g2][hf], Bl[g2][hf + 1]);
                    mma16816(c[mi][ni], Al[mi], Bh[g2][hf], Bh[g2][hf + 1]);
                }
        }
    };

    load_chunk(0, sb);
    for (int kc = 0; kc < nk; kc++) {
        uint32_t stg  = sb + (uint32_t)(kc & 1) * STAGE;
        uint32_t nstg = sb + (uint32_t)((kc & 1) ^ 1) * STAGE;
        if (kc + 1 < nk) { load_chunk(kc + 1, nstg); CP_WAIT(1); }
        else             { CP_WAIT(0); }
        __syncthreads();
        compute(stg);
        __syncthreads();
    }

    // epilogue: stage to smem, coalesced store + bias
    float* esm = (float*)smem;
    #pragma unroll
    for (int mi = 0; mi < 4; mi++)
        #pragma unroll
        for (int ni = 0; ni < 4; ni++) {
            int row = RB + mi * 16 + (lane >> 2);
            int col = CB + ni * 8 + (lane & 3) * 2;
            esm[row * 132 + col]           = c[mi][ni][0];
            esm[row * 132 + col + 1]       = c[mi][ni][1];
            esm[(row + 8) * 132 + col]     = c[mi][ni][2];
            esm[(row + 8) * 132 + col + 1] = c[mi][ni][3];
        }
    __syncthreads();
    #pragma unroll
    for (int it = 0; it < 16; it++) {
        int r = it * 8 + (tid >> 5);
        int nb = lane * 4;
        float4 v = *(float4*)&esm[r * 132 + nb];
        int n = n0 + nb;
        size_t o = (size_t)(m0 + r) * ldc;
        if (n + 3 < Nvalid && (((o + n) & 3) == 0)) {
            v.x += bias[n]; v.y += bias[n + 1]; v.z += bias[n + 2]; v.w += bias[n + 3];
            *(float4*)&C[o + n] = v;
        } else {
            float vv[4] = {v.x, v.y, v.z, v.w};
            #pragma unroll
            for (int j = 0; j < 4; j++)
                if (n + j < Nvalid) C[o + n + j] = vv[j] + bias[n + j];
        }
    }
}

// ============================================================================
// HMMA fused LSTM step: gates[64 x 64tile] = h @ WhhPerm^T, + xg, activations.
// Tile 64x64, BK=32, 128 threads (4 warps, warp tile 64x16). grid = 72.
// Weight columns gate-interleaved: col 4j+g = gate g of cell j.
// ============================================================================
__global__ __launch_bounds__(128, 1)
void hmma_lstm(const __nv_bfloat16* __restrict__ hHi, const __nv_bfloat16* __restrict__ hLo,
               const __nv_bfloat16* __restrict__ wHi, const __nv_bfloat16* __restrict__ wLo,
               const float* __restrict__ xg_t,
               const float* __restrict__ c_in, float* __restrict__ c_out,
               __nv_bfloat16* __restrict__ hHiOut, __nv_bfloat16* __restrict__ hLoOut,
               float* __restrict__ hs_out)
{
    extern __shared__ __align__(16) char smem[];
    uint32_t sb = smem_to_u32(smem);
    const int tid = threadIdx.x, lane = tid & 31, wid = tid >> 5;
    const int CB = wid * 16;
    const int n0 = blockIdx.x * 64;
    const int STAGE = 20480, TILE = 5120;

    float c[4][2][4];
    #pragma unroll
    for (int i = 0; i < 4; i++)
        #pragma unroll
        for (int j = 0; j < 2; j++)
            #pragma unroll
            for (int k = 0; k < 4; k++) c[i][j][k] = 0.f;

    auto load_chunk = [&](int kc, uint32_t stg) {
        #pragma unroll
        for (int i = 0; i < 8; i++) {
            int idx = tid + i * 128;
            int tile = idx >> 8, w = idx & 255, row = w >> 2, cc = w & 3;
            const __nv_bfloat16* g = (tile == 0) ? hHi : (tile == 1) ? hLo : (tile == 2) ? wHi : wLo;
            int grow = ((tile < 2) ? 0 : n0) + row;
            cp16(stg + tile * TILE + row * 80 + cc * 16,
                 g + (size_t)grow * KP + kc * 32 + cc * 8);
        }
        CP_COMMIT();
    };

    auto compute = [&](uint32_t stg) {
        #pragma unroll
        for (int ks = 0; ks < 2; ks++) {
            int kb = ks * 16;
            uint32_t Ah[4][4], Al[4][4], Bh[4], Bl[4];
            #pragma unroll
            for (int mi = 0; mi < 4; mi++) {
                uint32_t off = (uint32_t)(mi * 16 + (lane & 15)) * 80
                             + (uint32_t)(kb + ((lane >> 4) << 3)) * 2;
                ldm4(stg + off, Ah[mi]);
                ldm4(stg + TILE + off, Al[mi]);
            }
            {
                uint32_t nrow = CB + (lane & 7) + ((lane >> 4) & 1) * 8;
                uint32_t off = nrow * 80 + (uint32_t)(kb + ((lane >> 3) & 1) * 8) * 2;
                ldm4(stg + 2 * TILE + off, Bh);
                ldm4(stg + 3 * TILE + off, Bl);
            }
            #pragma unroll
            for (int mi = 0; mi < 4; mi++)
                #pragma unroll
                for (int ni = 0; ni < 2; ni++) {
                    int hf = ni * 2;
                    mma16816(c[mi][ni], Ah[mi], Bh[hf], Bh[hf + 1]);
                    mma16816(c[mi][ni], Ah[mi], Bl[hf], Bl[hf + 1]);
                    mma16816(c[mi][ni], Al[mi], Bh[hf], Bh[hf + 1]);
                }
        }
    };

    load_chunk(0, sb);
    const int nk = KP / 32;  // 36
    for (int kc = 0; kc < nk; kc++) {
        uint32_t stg  = sb + (uint32_t)(kc & 1) * STAGE;
        uint32_t nstg = sb + (uint32_t)((kc & 1) ^ 1) * STAGE;
        if (kc + 1 < nk) { load_chunk(kc + 1, nstg); CP_WAIT(1); }
        else             { CP_WAIT(0); }
        __syncthreads();
        compute(stg);
        __syncthreads();
    }

    float* esm = (float*)smem;
    #pragma unroll
    for (int mi = 0; mi < 4; mi++)
        #pragma unroll
        for (int ni = 0; ni < 2; ni++) {
            int row = mi * 16 + (lane >> 2);
            int col = CB + ni * 8 + (lane & 3) * 2;
            esm[row * 68 + col]           = c[mi][ni][0];
            esm[row * 68 + col + 1]       = c[mi][ni][1];
            esm[(row + 8) * 68 + col]     = c[mi][ni][2];
            esm[(row + 8) * 68 + col + 1] = c[mi][ni][3];
        }
    __syncthreads();

    const int cell0 = blockIdx.x * 16;
    #pragma unroll
    for (int it = 0; it < 8; it++) {
        int task = it * 128 + tid;   // 0..1023
        int b = task >> 4, jl = task & 15;
        int cell = cell0 + jl;
        if (cell < NHID) {
            const float* gg = esm + b * 68 + 4 * jl;
            const float* xr = xg_t + (size_t)b * G4P + n0 + 4 * jl;
            float vi = gg[0] + xr[0];
            float vf = gg[1] + xr[1];
            float vg = gg[2] + xr[2];
            float vo = gg[3] + xr[3];
            float ii = 1.f / (1.f + expf(-vi));
            float ff = 1.f / (1.f + expf(-vf));
            float gt = tanhf(vg);
            float oo = 1.f / (1.f + expf(-vo));
            float cn = ff * c_in[b * NHID + cell] + ii * gt;
            float hn = oo * tanhf(cn);
            c_out[b * NHID + cell] = cn;
            hs_out[(size_t)b * NHID + cell] = hn;
            __nv_bfloat16 hh = __float2bfloat16(hn);
            hHiOut[b * KP + cell] = hh;
            hLoOut[b * KP + cell] = __float2bfloat16(hn - __bfloat162float(hh));
        }
    }
}

// ---------------- conversion kernels ----------------
__global__ void split_pad(const float* __restrict__ src, int M, int K, int ldsrc,
                          __nv_bfloat16* __restrict__ hi, __nv_bfloat16* __restrict__ lo, int MP)
{
    size_t idx = (size_t)blockIdx.x * blockDim.x + threadIdx.x;
    if (idx >= (size_t)MP * KP) return;
    int m = (int)(idx / KP), k = (int)(idx % KP);
    float v = (m < M && k < K) ? src[(size_t)m * ldsrc + k] : 0.f;
    __nv_bfloat16 h = __float2bfloat16(v);
    hi[idx] = h;
    lo[idx] = __float2bfloat16(v - __bfloat162float(h));
}

__global__ void split_perm_w(const float* __restrict__ W, int Ksrc,
                             __nv_bfloat16* __restrict__ hi, __nv_bfloat16* __restrict__ lo)
{
    size_t idx = (size_t)blockIdx.x * blockDim.x + threadIdx.x;
    if (idx >= (size_t)G4P * KP) return;
    int r = (int)(idx / KP), k = (int)(idx % KP);
    int j = r >> 2, g = r & 3;
    float v = (j < NHID && k < Ksrc) ? W[((size_t)g * NHID + j) * Ksrc + k] : 0.f;
    __nv_bfloat16 h = __float2bfloat16(v);
    hi[idx] = h;
    lo[idx] = __float2bfloat16(v - __bfloat162float(h));
}

__global__ void bias_perm(const float* __restrict__ bih, const float* __restrict__ bhh,
                          float* __restrict__ bp)
{
    int r = blockIdx.x * blockDim.x + threadIdx.x;
    if (r >= G4P) return;
    int j = r >> 2, g = r & 3;
    bp[r] = (j < NHID) ? bih[g * NHID + j] + bhh[g * NHID + j] : 0.f;
}

__global__ void init_h(const float* __restrict__ h0,
                       __nv_bfloat16* __restrict__ hhi, __nv_bfloat16* __restrict__ hlo)
{
    int idx = blockIdx.x * blockDim.x + threadIdx.x;
    if (idx >= 2 * 64 * KP) return;
    int within = idx % (64 * KP);
    int r = within / KP, k = within % KP;
    float v = (idx < 64 * KP && k < NHID) ? h0[r * NHID + k] : 0.f;
    __nv_bfloat16 h = __float2bfloat16(v);
    hhi[idx] = h;
    hlo[idx] = __float2bfloat16(v - __bfloat162float(h));
}

__global__ void init_c(const float* __restrict__ c0, float* __restrict__ c)
{
    int i = blockIdx.x * blockDim.x + threadIdx.x;
    if (i < BATCH * NHID) c[i] = c0[i];
}

__global__ void embed_kernel(const int* __restrict__ in1, const int* __restrict__ in2,
                             const float* __restrict__ embW, float* __restrict__ x0)
{
    int m = blockIdx.x;
    const float* e1 = embW + (size_t)in1[m] * NINP;
    const float* e2 = embW + (size_t)in2[m] * NINP;
    float* row = x0 + (size_t)m * (2 * NINP);
    for (int k = threadIdx.x; k < NINP; k += blockDim.x) {
        row[k] = e1[k];
        row[NINP + k] = e2[k];
    }
}

// ---------------- attention (SIMT fp32) ----------------
__global__ __launch_bounds__(128)
void attention_kernel(const float* __restrict__ hs, float* __restrict__ out)
{
    int b = blockIdx.x, t = blockIdx.y;
    const int H = NHID;
    __shared__ float ht[NHID];
    __shared__ float sc[T_STEPS];
    __shared__ float red[128];
    int tid = threadIdx.x;
    const float* hsb = hs + (size_t)b * H;
    for (int k = tid; k < H; k += 128) ht[k] = hsb[(size_t)t * BATCH * H + k];
    __syncthreads();
    float lmax = -1e30f;
    for (int s = tid; s <= t; s += 128) {
        const float* row = hsb + (size_t)s * BATCH * H;
        float d = 0.f;
        for (int k = 0; k < H; k++) d += ht[k] * row[k];
        sc[s] = d;
        lmax = fmaxf(lmax, d);
    }
    red[tid] = lmax; __syncthreads();
    #pragma unroll
    for (int o = 64; o > 0; o >>= 1) { if (tid < o) red[tid] = fmaxf(red[tid], red[tid + o]); __syncthreads(); }
    float mx = red[0]; __syncthreads();
    float lsum = 0.f;
    for (int s = tid; s <= t; s += 128) { float e = expf(sc[s] - mx); sc[s] = e; lsum += e; }
    red[tid] = lsum; __syncthreads();
    #pragma unroll
    for (int o = 64; o > 0; o >>= 1) { if (tid < o) red[tid] += red[tid + o]; __syncthreads(); }
    float inv = 1.f / red[0]; __syncthreads();
    for (int h = tid; h < H; h += 128) {
        float a = 0.f;
        for (int s = 0; s <= t; s++) a += sc[s] * hsb[(size_t)s * BATCH * H + h];
        out[((size_t)t * BATCH + b) * H + h] = a * inv;
    }
}

// ---------------- launch ----------------
static void* sym_addr(const void* s) { void* p = nullptr; cudaGetSymbolAddress(&p, s); return p; }

extern "C" void kernel_launch(void* const* d_in, const int* in_sizes, int n_in,
                              void* d_out, int out_size)
{
    const int SMEM_GEMM = 2 * 40960;  // 81920
    const int SMEM_LSTM = 2 * 20480;  // 40960
    cudaFuncSetAttribute(hmma_gemm, cudaFuncAttributeMaxDynamicSharedMemorySize, SMEM_GEMM);
    cudaFuncSetAttribute(hmma_lstm, cudaFuncAttributeMaxDynamicSharedMemorySize, SMEM_LSTM);

    const int* in1 = (const int*)d_in[0];
    const int* in2 = (const int*)d_in[1];
    const float* hc0[6] = { (const float*)d_in[2], (const float*)d_in[3],
                            (const float*)d_in[4], (const float*)d_in[5],
                            (const float*)d_in[6], (const float*)d_in[7] };
    const float* embW = (const float*)d_in[8];
    const float *W_ih[3], *W_hh[3], *b_ih[3], *b_hh[3];
    for (int l = 0; l < 3; l++) {
        W_ih[l] = (const float*)d_in[9 + 4*l];
        W_hh[l] = (const float*)d_in[10 + 4*l];
        b_ih[l] = (const float*)d_in[11 + 4*l];
        b_hh[l] = (const float*)d_in[12 + 4*l];
    }
    const float* decW = (const float*)d_in[21];
    const float* decb = (const float*)d_in[22];
    float* out = (float*)d_out;

    float* x0   = (float*)sym_addr(g_x0);
    float* xg   = (float*)sym_addr(g_xg);
    float* hs1  = (float*)sym_addr(g_hs1);
    float* hs2  = (float*)sym_addr(g_hs2);
    float* att  = (float*)sym_addr(g_att);
    float* cbuf = (float*)sym_addr(g_c);
    float* bperm = (float*)sym_addr(g_bperm);
    __nv_bfloat16* aHi = (__nv_bfloat16*)sym_addr(g_a_hi);
    __nv_bfloat16* aLo = (__nv_bfloat16*)sym_addr(g_a_lo);
    __nv_bfloat16* dHi = (__nv_bfloat16*)sym_addr(g_dec_hi);
    __nv_bfloat16* dLo = (__nv_bfloat16*)sym_addr(g_dec_lo);
    __nv_bfloat16* wihHi = (__nv_bfloat16*)sym_addr(g_wih_hi);
    __nv_bfloat16* wihLo = (__nv_bfloat16*)sym_addr(g_wih_lo);
    __nv_bfloat16* whhHi = (__nv_bfloat16*)sym_addr(g_whh_hi);
    __nv_bfloat16* whhLo = (__nv_bfloat16*)sym_addr(g_whh_lo);
    __nv_bfloat16* hHi = (__nv_bfloat16*)sym_addr(g_h_hi);
    __nv_bfloat16* hLo = (__nv_bfloat16*)sym_addr(g_h_lo);

    const int HC = BATCH * NHID;
    const int HB = 64 * KP;

    // decoder weight split
    {
        size_t tot = (size_t)NTOK_P * KP;
        split_pad<<<(unsigned)((tot + 255) / 256), 256>>>(decW, NTOKEN, NHID, NHID, dHi, dLo, NTOK_P);
    }
    embed_kernel<<<MB, 256>>>(in1, in2, embW, x0);

    const float* layer_in[3]  = { x0, hs1, hs2 };
    const int    layer_K[3]   = { 2 * NINP, NHID, NHID };
    float*       layer_out[3] = { hs1, hs2, hs1 };

    for (int l = 0; l < 3; l++) {
        size_t atot = (size_t)MB * KP;
        split_pad<<<(unsigned)((atot + 255) / 256), 256>>>(layer_in[l], MB, layer_K[l], layer_K[l], aHi, aLo, MB);
        size_t wtot = (size_t)G4P * KP;
        split_perm_w<<<(unsigned)((wtot + 255) / 256), 256>>>(W_ih[l], layer_K[l], wihHi, wihLo);
        split_perm_w<<<(unsigned)((wtot + 255) / 256), 256>>>(W_hh[l], NHID, whhHi, whhLo);
        bias_perm<<<(G4P + 255) / 256, 256>>>(b_ih[l], b_hh[l], bperm);

        int nk_in = (layer_K[l] + 31) / 32;   // 25 for layer0, 36 otherwise
        dim3 ggrid(MB / 128, G4P / 128);
        hmma_gemm<<<ggrid, 256, SMEM_GEMM>>>(aHi, aLo, wihHi, wihLo, xg, bperm, nk_in, G4P, G4P);

        init_h<<<(2 * HB + 255) / 256, 256>>>(hc0[2 * l], hHi, hLo);
        init_c<<<(HC + 255) / 256, 256>>>(hc0[2 * l + 1], cbuf);

        for (int t = 0; t < T_STEPS; t++) {
            int pi = t & 1, po = (t + 1) & 1;
            hmma_lstm<<<G4P / 64, 128, SMEM_LSTM>>>(
                hHi + pi * HB, hLo + pi * HB, whhHi, whhLo,
                xg + (size_t)t * BATCH * G4P,
                cbuf + pi * HC, cbuf + po * HC,
                hHi + po * HB, hLo + po * HB,
                layer_out[l] + (size_t)t * BATCH * NHID);
        }
    }

    attention_kernel<<<dim3(BATCH, T_STEPS), 128>>>(hs1, att);

    size_t atot = (size_t)MB * KP;
    split_pad<<<(unsigned)((atot + 255) / 256), 256>>>(att, MB, NHID, NHID, aHi, aLo, MB);
    dim3 dgrid(MB / 128, NTOK_P / 128);
    hmma_gemm<<<dgrid, 256, SMEM_GEMM>>>(aHi, aLo, dHi, dLo, out, decb, KP / 32, NTOKEN, NTOKEN);
}